// round 12
// baseline (speedup 1.0000x reference)
#include <cuda_runtime.h>
#include <cstdint>

// FISTA denoiser: packed adds (add2) + scalar FFMA-imm coefficient chains
// (rt=1, bank-conflict-free), ghost-boundary uniform 5-point stencil.
// One warp = two rows; each u64 register packs (row0[i], row1[i]).

#define LAM   10.0f
#define NIT   100
#define ROWN  512
#define EPL   16

typedef unsigned long long u64;

__device__ __forceinline__ u64 pk(float lo, float hi) {
    u64 r; asm("mov.b64 %0, {%1,%2};" : "=l"(r) : "f"(lo), "f"(hi)); return r;
}
__device__ __forceinline__ void upk(u64 v, float& lo, float& hi) {
    asm("mov.b64 {%0,%1}, %2;" : "=f"(lo), "=f"(hi) : "l"(v));
}
__device__ __forceinline__ u64 fma2(u64 a, u64 b, u64 c) {
    u64 d; asm("fma.rn.f32x2 %0, %1, %2, %3;" : "=l"(d) : "l"(a), "l"(b), "l"(c)); return d;
}
__device__ __forceinline__ u64 add2(u64 a, u64 b) {
    u64 d; asm("add.rn.f32x2 %0, %1, %2;" : "=l"(d) : "l"(a), "l"(b)); return d;
}
__device__ __forceinline__ u64 mul2(u64 a, u64 b) {
    u64 d; asm("mul.rn.f32x2 %0, %1, %2;" : "=l"(d) : "l"(a), "l"(b)); return d;
}
__device__ __forceinline__ u64 bc(float f) { return pk(f, f); }

// A = 1/(1+16*LAM) = 2*step ; B = LAM/(1+16*LAM) = 2*LAM*step
// 5-point taps: C0 = 1-A-6B, C1 = 4B, C2 = -B  (as compile-time literals
// so ptxas emits FFMA-imm, rt=1, 2 register reads -> no RF bank conflicts)
#define CAf (1.0f / 161.0f)
#define C0f (100.0f / 161.0f)
#define C1f (40.0f / 161.0f)
#define C2f (-10.0f / 161.0f)

// ---- compile-time FISTA momentum table, pre-broadcast as u64 f32x2 pairs ----
constexpr u64 bcast_bits(float f) {
    unsigned b = __builtin_bit_cast(unsigned, f);
    return ((u64)b << 32) | (u64)b;
}
struct MTab { u64 m1p[NIT]; u64 mn[NIT]; };
constexpr MTab make_mtab() {
    MTab t{};
    double tt = 1.0;
    for (int i = 0; i < NIT; i++) {
        double s = 1.0 + 4.0 * tt * tt;
        double r = s;                         // Newton sqrt
        for (int k = 0; k < 64; k++) r = 0.5 * (r + s / r);
        double tn = 0.5 * (1.0 + r);
        double m  = (tt - 1.0) / tn;
        t.m1p[i] = bcast_bits((float)(1.0 + m));
        t.mn[i]  = bcast_bits((float)(-m));
        tt = tn;
    }
    return t;
}
__constant__ MTab c_mtab = make_mtab();

// One FISTA solve on the packed pair-of-rows. y: data (packed), x: output (packed).
__device__ __forceinline__ void solve2(const u64* __restrict__ y,
                                       u64* __restrict__ x,
                                       int lane)
{
    const unsigned FULL = 0xffffffffu;
    const u64 NEG1 = bc(-1.0f);

    u64 z[EPL];
    #pragma unroll
    for (int i = 0; i < EPL; i++) { x[i] = y[i]; z[i] = y[i]; }  // proj(y)=y on [0,y]

    const bool l0 = (lane == 0), l31 = (lane == 31);

    #pragma unroll 2
    for (int it = 0; it < NIT; ++it) {
        // 64-bit halo shuffles
        u64 zm2 = __shfl_up_sync  (FULL, z[EPL - 2], 1);
        u64 zm1 = __shfl_up_sync  (FULL, z[EPL - 1], 1);
        u64 zp0 = __shfl_down_sync(FULL, z[0], 1);
        u64 zp1 = __shfl_down_sync(FULL, z[1], 1);

        // ghost values making the uniform stencil exact at the boundaries
        {
            u64 dl  = fma2(NEG1, z[1], z[0]);              // z0 - z1
            u64 g1  = add2(z[0], dl);                      // 2 z0 - z1
            u64 g2  = add2(g1,  dl);                       // 3 z0 - 2 z1
            u64 dr  = fma2(NEG1, z[EPL - 2], z[EPL - 1]);  // z15 - z14
            u64 g3  = add2(z[EPL - 1], dr);                // 2 z15 - z14
            u64 g4  = add2(g3, dr);                        // 3 z15 - 2 z14
            zm1 = l0  ? g1 : zm1;
            zm2 = l0  ? g2 : zm2;
            zp0 = l31 ? g3 : zp0;
            zp1 = l31 ? g4 : zp1;
        }

        // ze[k] = z_ext[16*lane - 2 + k], k = 0..19  (snapshot of z)
        u64 ze[EPL + 4];
        ze[0] = zm2; ze[1] = zm1;
        #pragma unroll
        for (int i = 0; i < EPL; i++) ze[2 + i] = z[i];
        ze[EPL + 2] = zp0; ze[EPL + 3] = zp1;

        // momentum coefficients (pre-broadcast u64 pairs, one LDC.64 each)
        const u64 M1P = c_mtab.m1p[it];
        const u64 MN  = c_mtab.mn[it];

        // branch-free element loop:
        //   packed adds for the symmetric sums, scalar FFMA-imm chains for
        //   the coefficient terms (rt=1, conflict-free), scalar clamp,
        //   packed momentum.
        #pragma unroll
        for (int i = 0; i < EPL; i++) {
            u64 s1p = add2(ze[i + 1], ze[i + 3]);   // z[-1] + z[+1]
            u64 s2p = add2(ze[i],     ze[i + 4]);   // z[-2] + z[+2]

            float s1l, s1h, s2l, s2h, zcl, zch, yl, yh;
            upk(s1p, s1l, s1h);
            upk(s2p, s2l, s2h);
            upk(ze[i + 2], zcl, zch);
            upk(y[i], yl, yh);

            // v = CA*y + C2*s2 + C1*s1 + C0*zc   (all-literal multipliers)
            float vl = fmaf(zcl, C0f, fmaf(s1l, C1f, fmaf(s2l, C2f, yl * CAf)));
            float vh = fmaf(zch, C0f, fmaf(s1h, C1f, fmaf(s2h, C2f, yh * CAf)));

            // clamp onto [0, y] — scalar FMNMX pairs on alu pipe
            float xl = fminf(fmaxf(vl, 0.0f), yl);
            float xh = fminf(fmaxf(vh, 0.0f), yh);
            u64 xn = pk(xl, xh);

            // z_new = (1+m) x_new - m x_old   (runtime coeffs -> packed)
            u64 zn = fma2(M1P, xn, mul2(MN, x[i]));
            x[i] = xn;
            z[i] = zn;
        }
    }
}

__global__ void __launch_bounds__(128, 4)
fista_denoise12_kernel(const float* __restrict__ in, float* __restrict__ out, int npairs)
{
    const int gwarp = (int)((blockIdx.x * (unsigned)blockDim.x + threadIdx.x) >> 5);
    const int lane  = threadIdx.x & 31;
    if (gwarp >= npairs) return;   // whole warp exits together

    const float* r0 = in + (size_t)(2 * gwarp) * ROWN + lane * EPL;
    const float* r1 = r0 + ROWN;

    u64 y[EPL];
    #pragma unroll
    for (int v = 0; v < EPL / 4; v++) {
        float4 a = reinterpret_cast<const float4*>(r0)[v];
        float4 b = reinterpret_cast<const float4*>(r1)[v];
        y[4 * v + 0] = pk(a.x, b.x);
        y[4 * v + 1] = pk(a.y, b.y);
        y[4 * v + 2] = pk(a.z, b.z);
        y[4 * v + 3] = pk(a.w, b.w);
    }

    u64 x[EPL];
    solve2(y, x, lane);                       // pass 1: y = input
    #pragma unroll
    for (int i = 0; i < EPL; i++) y[i] = x[i];
    solve2(y, x, lane);                       // pass 2: y = pass-1 output

    float* w0 = out + (size_t)(2 * gwarp) * ROWN + lane * EPL;
    float* w1 = w0 + ROWN;
    #pragma unroll
    for (int v = 0; v < EPL / 4; v++) {
        float4 a, b;
        upk(x[4 * v + 0], a.x, b.x);
        upk(x[4 * v + 1], a.y, b.y);
        upk(x[4 * v + 2], a.z, b.z);
        upk(x[4 * v + 3], a.w, b.w);
        reinterpret_cast<float4*>(w0)[v] = a;
        reinterpret_cast<float4*>(w1)[v] = b;
    }
}

extern "C" void kernel_launch(void* const* d_in, const int* in_sizes, int n_in,
                              void* d_out, int out_size)
{
    const float* in = (const float*)d_in[0];
    float* out = (float*)d_out;
    const int nelem  = in_sizes[0];           // 32*512*512
    const int nrows  = nelem / ROWN;          // 16384
    const int npairs = nrows / 2;             // 8192 warps
    const int warps_per_block = 128 / 32;     // 4
    const int nblocks = (npairs + warps_per_block - 1) / warps_per_block;
    fista_denoise12_kernel<<<nblocks, 128>>>(in, out, npairs);
}

// round 13
// speedup vs baseline: 1.0626x; 1.0626x over previous
#include <cuda_runtime.h>
#include <cstdint>

// FISTA denoiser, scaled-variable form: X = 161*x, Z = 161*z so the data
// term enters with coefficient 1 (chain seed), killing one packed op/elem.
// Packed f32x2 stencil + ghost boundaries; y seed in smem (plain LDS, chain
// head -> latency-free); clamp bound Y161 = 161*y in registers.
// One warp = two rows; each u64 register packs (row0[i], row1[i]).

#define LAM   10.0f
#define NIT   100
#define ROWN  512
#define EPL   16
#define TPB   128

typedef unsigned long long u64;

__device__ __forceinline__ u64 pk(float lo, float hi) {
    u64 r; asm("mov.b64 %0, {%1,%2};" : "=l"(r) : "f"(lo), "f"(hi)); return r;
}
__device__ __forceinline__ void upk(u64 v, float& lo, float& hi) {
    asm("mov.b64 {%0,%1}, %2;" : "=f"(lo), "=f"(hi) : "l"(v));
}
__device__ __forceinline__ u64 fma2(u64 a, u64 b, u64 c) {
    u64 d; asm("fma.rn.f32x2 %0, %1, %2, %3;" : "=l"(d) : "l"(a), "l"(b), "l"(c)); return d;
}
__device__ __forceinline__ u64 add2(u64 a, u64 b) {
    u64 d; asm("add.rn.f32x2 %0, %1, %2;" : "=l"(d) : "l"(a), "l"(b)); return d;
}
__device__ __forceinline__ u64 mul2(u64 a, u64 b) {
    u64 d; asm("mul.rn.f32x2 %0, %1, %2;" : "=l"(d) : "l"(a), "l"(b)); return d;
}
__device__ __forceinline__ u64 bc(float f) { return pk(f, f); }

// 5-point taps (scale-invariant): C0 = 100/161, C1 = 40/161, C2 = -10/161
#define SCL   161.0f
#define ISCL  (1.0f / 161.0f)

// ---- compile-time FISTA momentum table, pre-broadcast as u64 f32x2 pairs ----
constexpr u64 bcast_bits(float f) {
    unsigned b = __builtin_bit_cast(unsigned, f);
    return ((u64)b << 32) | (u64)b;
}
struct MTab { u64 m1p[NIT]; u64 mn[NIT]; };
constexpr MTab make_mtab() {
    MTab t{};
    double tt = 1.0;
    for (int i = 0; i < NIT; i++) {
        double s = 1.0 + 4.0 * tt * tt;
        double r = s;                         // Newton sqrt
        for (int k = 0; k < 64; k++) r = 0.5 * (r + s / r);
        double tn = 0.5 * (1.0 + r);
        double m  = (tt - 1.0) / tn;
        t.m1p[i] = bcast_bits((float)(1.0 + m));
        t.mn[i]  = bcast_bits((float)(-m));
        tt = tn;
    }
    return t;
}
__constant__ MTab c_mtab = make_mtab();

// One scaled FISTA solve.
//   ysh[i][tid] : unscaled y (data-term chain seed), read-only here
//   yb[]        : Y161 = 161*y packed (clamp bound; also exact X0 = Z0)
//   x[]         : scaled iterate X, output
__device__ __forceinline__ void solve2(const u64 (*__restrict__ ysh)[TPB],
                                       int tid, int lane,
                                       const u64* __restrict__ yb,
                                       u64* __restrict__ x)
{
    const unsigned FULL = 0xffffffffu;
    const u64 C0   = bc(100.0f / 161.0f);
    const u64 C1   = bc(40.0f / 161.0f);
    const u64 C2   = bc(-10.0f / 161.0f);
    const u64 NEG1 = bc(-1.0f);

    u64 z[EPL];
    #pragma unroll
    for (int i = 0; i < EPL; i++) { x[i] = yb[i]; z[i] = yb[i]; }  // X0 = Z0 = 161*proj(y)

    const bool l0 = (lane == 0), l31 = (lane == 31);

    for (int it = 0; it < NIT; ++it) {
        // 64-bit halo shuffles
        u64 zm2 = __shfl_up_sync  (FULL, z[EPL - 2], 1);
        u64 zm1 = __shfl_up_sync  (FULL, z[EPL - 1], 1);
        u64 zp0 = __shfl_down_sync(FULL, z[0], 1);
        u64 zp1 = __shfl_down_sync(FULL, z[1], 1);

        // ghost values making the uniform stencil exact at the boundaries
        // (linear in Z -> identical formulas in scaled space)
        {
            u64 dl  = fma2(NEG1, z[1], z[0]);              // Z0 - Z1
            u64 g1  = add2(z[0], dl);                      // 2 Z0 - Z1
            u64 g2  = add2(g1,  dl);                       // 3 Z0 - 2 Z1
            u64 dr  = fma2(NEG1, z[EPL - 2], z[EPL - 1]);  // Z15 - Z14
            u64 g3  = add2(z[EPL - 1], dr);                // 2 Z15 - Z14
            u64 g4  = add2(g3, dr);                        // 3 Z15 - 2 Z14
            zm1 = l0  ? g1 : zm1;
            zm2 = l0  ? g2 : zm2;
            zp0 = l31 ? g3 : zp0;
            zp1 = l31 ? g4 : zp1;
        }

        // ze[k] = Z_ext[16*lane - 2 + k], k = 0..19  (snapshot of Z)
        u64 ze[EPL + 4];
        ze[0] = zm2; ze[1] = zm1;
        #pragma unroll
        for (int i = 0; i < EPL; i++) ze[2 + i] = z[i];
        ze[EPL + 2] = zp0; ze[EPL + 3] = zp1;

        // momentum coefficients (pre-broadcast u64 pairs, one LDC.64 each)
        const u64 M1P = c_mtab.m1p[it];
        const u64 MN  = c_mtab.mn[it];

        // branch-free element loop: 5 packed stencil ops (y seeds the chain,
        // coefficient exactly 1 in scaled space) + scalar clamp + 2 packed.
        #pragma unroll
        for (int i = 0; i < EPL; i++) {
            u64 yv = ysh[i][tid];                   // chain seed, early & slack-rich

            // V = y + C0*Zc + C1*(Z[-1]+Z[+1]) + C2*(Z[-2]+Z[+2])
            u64 s1 = add2(ze[i + 1], ze[i + 3]);
            u64 s2 = add2(ze[i],     ze[i + 4]);
            u64 v  = fma2(C0, ze[i + 2],
                       fma2(C1, s1,
                         fma2(C2, s2, yv)));

            // clamp onto [0, 161*y] — scalar FMNMX pairs on alu pipe
            float vl, vh, bl, bh;
            upk(v, vl, vh);
            upk(yb[i], bl, bh);
            float xl = fminf(fmaxf(vl, 0.0f), bl);
            float xh = fminf(fmaxf(vh, 0.0f), bh);
            u64 xn = pk(xl, xh);

            // Z_new = (1+m) X_new - m X_old
            u64 zn = fma2(M1P, xn, mul2(MN, x[i]));
            x[i] = xn;
            z[i] = zn;
        }
    }
}

__global__ void __launch_bounds__(TPB, 4)
fista_denoise13_kernel(const float* __restrict__ in, float* __restrict__ out, int npairs)
{
    __shared__ u64 ysh[EPL][TPB];

    const int tid   = threadIdx.x;
    const int gwarp = (int)((blockIdx.x * (unsigned)blockDim.x + tid) >> 5);
    const int lane  = tid & 31;
    if (gwarp >= npairs) return;   // whole warp exits together

    const float* r0 = in + (size_t)(2 * gwarp) * ROWN + lane * EPL;
    const float* r1 = r0 + ROWN;

    const u64 S  = bc(SCL);
    const u64 IS = bc(ISCL);

    // pack input pair-of-rows; stage y (unscaled) in smem, Y161 in registers
    u64 yb[EPL];
    #pragma unroll
    for (int v = 0; v < EPL / 4; v++) {
        float4 a = reinterpret_cast<const float4*>(r0)[v];
        float4 b = reinterpret_cast<const float4*>(r1)[v];
        u64 p0 = pk(a.x, b.x), p1 = pk(a.y, b.y);
        u64 p2 = pk(a.z, b.z), p3 = pk(a.w, b.w);
        ysh[4 * v + 0][tid] = p0;
        ysh[4 * v + 1][tid] = p1;
        ysh[4 * v + 2][tid] = p2;
        ysh[4 * v + 3][tid] = p3;
        yb[4 * v + 0] = mul2(S, p0);
        yb[4 * v + 1] = mul2(S, p1);
        yb[4 * v + 2] = mul2(S, p2);
        yb[4 * v + 3] = mul2(S, p3);
    }

    u64 x[EPL];
    solve2(ysh, tid, lane, yb, x);            // pass 1 (scaled)

    // pass 2: y2 = x1 = X1/161 ; Y161_2 = X1 exactly
    #pragma unroll
    for (int i = 0; i < EPL; i++) {
        ysh[i][tid] = mul2(IS, x[i]);
        yb[i] = x[i];
    }
    solve2(ysh, tid, lane, yb, x);            // pass 2 (scaled)

    // unscale and store
    float* w0 = out + (size_t)(2 * gwarp) * ROWN + lane * EPL;
    float* w1 = w0 + ROWN;
    #pragma unroll
    for (int v = 0; v < EPL / 4; v++) {
        float4 a, b;
        u64 q0 = mul2(IS, x[4 * v + 0]);
        u64 q1 = mul2(IS, x[4 * v + 1]);
        u64 q2 = mul2(IS, x[4 * v + 2]);
        u64 q3 = mul2(IS, x[4 * v + 3]);
        upk(q0, a.x, b.x);
        upk(q1, a.y, b.y);
        upk(q2, a.z, b.z);
        upk(q3, a.w, b.w);
        reinterpret_cast<float4*>(w0)[v] = a;
        reinterpret_cast<float4*>(w1)[v] = b;
    }
}

extern "C" void kernel_launch(void* const* d_in, const int* in_sizes, int n_in,
                              void* d_out, int out_size)
{
    const float* in = (const float*)d_in[0];
    float* out = (float*)d_out;
    const int nelem  = in_sizes[0];           // 32*512*512
    const int nrows  = nelem / ROWN;          // 16384
    const int npairs = nrows / 2;             // 8192 warps
    const int warps_per_block = TPB / 32;     // 4
    const int nblocks = (npairs + warps_per_block - 1) / warps_per_block;
    fista_denoise13_kernel<<<nblocks, TPB>>>(in, out, npairs);
}

// round 14
// speedup vs baseline: 1.1491x; 1.0814x over previous
#include <cuda_runtime.h>
#include <cstdint>

// FISTA denoiser, packed f32x2, ghost-boundary uniform 5-point stencil.
// R9 core with overhead shaving: interior elements processed before edge
// elements (halo SHFL latency covered), momentum LDC prefetched 1 iter ahead.
// One warp = two rows; each u64 register packs (row0[i], row1[i]).

#define LAM   10.0f
#define NIT   100
#define ROWN  512
#define EPL   16

typedef unsigned long long u64;

__device__ __forceinline__ u64 pk(float lo, float hi) {
    u64 r; asm("mov.b64 %0, {%1,%2};" : "=l"(r) : "f"(lo), "f"(hi)); return r;
}
__device__ __forceinline__ void upk(u64 v, float& lo, float& hi) {
    asm("mov.b64 {%0,%1}, %2;" : "=f"(lo), "=f"(hi) : "l"(v));
}
__device__ __forceinline__ u64 fma2(u64 a, u64 b, u64 c) {
    u64 d; asm("fma.rn.f32x2 %0, %1, %2, %3;" : "=l"(d) : "l"(a), "l"(b), "l"(c)); return d;
}
__device__ __forceinline__ u64 add2(u64 a, u64 b) {
    u64 d; asm("add.rn.f32x2 %0, %1, %2;" : "=l"(d) : "l"(a), "l"(b)); return d;
}
__device__ __forceinline__ u64 mul2(u64 a, u64 b) {
    u64 d; asm("mul.rn.f32x2 %0, %1, %2;" : "=l"(d) : "l"(a), "l"(b)); return d;
}
__device__ __forceinline__ u64 bc(float f) { return pk(f, f); }

// A = 1/(1+16*LAM) = 2*step ; B = LAM/(1+16*LAM) = 2*LAM*step
#define C_A (1.0f / (1.0f + 16.0f * LAM))
#define C_B (LAM  / (1.0f + 16.0f * LAM))

// ---- compile-time FISTA momentum table, pre-broadcast as u64 f32x2 pairs ----
constexpr u64 bcast_bits(float f) {
    unsigned b = __builtin_bit_cast(unsigned, f);
    return ((u64)b << 32) | (u64)b;
}
struct MTab { u64 m1p[NIT + 1]; u64 mn[NIT + 1]; };
constexpr MTab make_mtab() {
    MTab t{};
    double tt = 1.0;
    for (int i = 0; i < NIT; i++) {
        double s = 1.0 + 4.0 * tt * tt;
        double r = s;                         // Newton sqrt
        for (int k = 0; k < 64; k++) r = 0.5 * (r + s / r);
        double tn = 0.5 * (1.0 + r);
        double m  = (tt - 1.0) / tn;
        t.m1p[i] = bcast_bits((float)(1.0 + m));
        t.mn[i]  = bcast_bits((float)(-m));
        tt = tn;
    }
    t.m1p[NIT] = t.m1p[NIT - 1];              // prefetch overrun slot
    t.mn[NIT]  = t.mn[NIT - 1];
    return t;
}
__constant__ MTab c_mtab = make_mtab();

// One FISTA solve on the packed pair-of-rows. y: data (packed), x: output (packed).
__device__ __forceinline__ void solve2(const u64* __restrict__ y,
                                       u64* __restrict__ x,
                                       int lane)
{
    const unsigned FULL = 0xffffffffu;
    const u64 C0  = bc(1.0f - C_A - 6.0f * C_B);   // center tap
    const u64 C1  = bc(4.0f * C_B);                // +/-1 taps
    const u64 C2  = bc(-C_B);                      // +/-2 taps
    const u64 CA  = bc(C_A);                       // data-term coefficient
    const u64 NEG1 = bc(-1.0f);

    u64 z[EPL];
    #pragma unroll
    for (int i = 0; i < EPL; i++) { x[i] = y[i]; z[i] = y[i]; }  // proj(y)=y on [0,y]

    const bool l0 = (lane == 0), l31 = (lane == 31);

    // momentum coefficient prefetch (1 iteration ahead)
    u64 M1P = c_mtab.m1p[0];
    u64 MN  = c_mtab.mn[0];

    // per-element update: clamp onto [0, y], momentum, writeback
    auto elem = [&](int i, u64 v, u64 m1p, u64 mn) {
        float vl, vh, yl, yh;
        upk(v, vl, vh);
        upk(y[i], yl, yh);
        float xl = fminf(fmaxf(vl, 0.0f), yl);
        float xh = fminf(fmaxf(vh, 0.0f), yh);
        u64 xn = pk(xl, xh);
        u64 zn = fma2(m1p, xn, mul2(mn, x[i]));
        x[i] = xn;
        z[i] = zn;
    };

    #pragma unroll 2
    for (int it = 0; it < NIT; ++it) {
        // 64-bit halo shuffles (consumed only by edge elements, processed last)
        u64 zm2 = __shfl_up_sync  (FULL, z[EPL - 2], 1);
        u64 zm1 = __shfl_up_sync  (FULL, z[EPL - 1], 1);
        u64 zp0 = __shfl_down_sync(FULL, z[0], 1);
        u64 zp1 = __shfl_down_sync(FULL, z[1], 1);

        const u64 M1Pc = M1P, MNc = MN;            // this iteration's coefficients
        M1P = c_mtab.m1p[it + 1];                  // prefetch next iteration's
        MN  = c_mtab.mn[it + 1];

        // snapshot of z (interior window only needs z itself)
        u64 ze[EPL];
        #pragma unroll
        for (int i = 0; i < EPL; i++) ze[i] = z[i];

        // ---- interior elements 2..13 first: no halo dependency ----
        #pragma unroll
        for (int i = 2; i < EPL - 2; i++) {
            u64 s1 = add2(ze[i - 1], ze[i + 1]);
            u64 s2 = add2(ze[i - 2], ze[i + 2]);
            u64 v  = fma2(CA, y[i],
                       fma2(C0, ze[i],
                         fma2(C1, s1, mul2(C2, s2))));
            elem(i, v, M1Pc, MNc);
        }

        // ---- ghost values (exact D^T D at rows 0,1,510,511) ----
        {
            u64 dl  = fma2(NEG1, ze[1], ze[0]);            // z0 - z1
            u64 g1  = add2(ze[0], dl);                     // 2 z0 - z1
            u64 g2  = add2(g1,  dl);                       // 3 z0 - 2 z1
            u64 dr  = fma2(NEG1, ze[EPL - 2], ze[EPL - 1]);
            u64 g3  = add2(ze[EPL - 1], dr);               // 2 z15 - z14
            u64 g4  = add2(g3, dr);                        // 3 z15 - 2 z14
            zm1 = l0  ? g1 : zm1;
            zm2 = l0  ? g2 : zm2;
            zp0 = l31 ? g3 : zp0;
            zp1 = l31 ? g4 : zp1;
        }

        // ---- edge elements 0, 1, 14, 15 last: halos had ~150 slots of cover ----
        {
            u64 s1 = add2(zm1, ze[1]);
            u64 s2 = add2(zm2, ze[2]);
            u64 v  = fma2(CA, y[0],
                       fma2(C0, ze[0], fma2(C1, s1, mul2(C2, s2))));
            elem(0, v, M1Pc, MNc);
        }
        {
            u64 s1 = add2(ze[0], ze[2]);
            u64 s2 = add2(zm1, ze[3]);
            u64 v  = fma2(CA, y[1],
                       fma2(C0, ze[1], fma2(C1, s1, mul2(C2, s2))));
            elem(1, v, M1Pc, MNc);
        }
        {
            u64 s1 = add2(ze[EPL - 3], ze[EPL - 1]);
            u64 s2 = add2(ze[EPL - 4], zp0);
            u64 v  = fma2(CA, y[EPL - 2],
                       fma2(C0, ze[EPL - 2], fma2(C1, s1, mul2(C2, s2))));
            elem(EPL - 2, v, M1Pc, MNc);
        }
        {
            u64 s1 = add2(ze[EPL - 2], zp0);
            u64 s2 = add2(ze[EPL - 3], zp1);
            u64 v  = fma2(CA, y[EPL - 1],
                       fma2(C0, ze[EPL - 1], fma2(C1, s1, mul2(C2, s2))));
            elem(EPL - 1, v, M1Pc, MNc);
        }
    }
}

__global__ void __launch_bounds__(128, 4)
fista_denoise14_kernel(const float* __restrict__ in, float* __restrict__ out)
{
    const int gwarp = (int)((blockIdx.x * (unsigned)blockDim.x + threadIdx.x) >> 5);
    const int lane  = threadIdx.x & 31;
    // grid exactly covers all pairs: no tail guard needed

    const float* r0 = in + (size_t)(2 * gwarp) * ROWN + lane * EPL;
    const float* r1 = r0 + ROWN;

    u64 y[EPL];
    #pragma unroll
    for (int v = 0; v < EPL / 4; v++) {
        float4 a = reinterpret_cast<const float4*>(r0)[v];
        float4 b = reinterpret_cast<const float4*>(r1)[v];
        y[4 * v + 0] = pk(a.x, b.x);
        y[4 * v + 1] = pk(a.y, b.y);
        y[4 * v + 2] = pk(a.z, b.z);
        y[4 * v + 3] = pk(a.w, b.w);
    }

    u64 x[EPL];
    solve2(y, x, lane);                       // pass 1: y = input
    #pragma unroll
    for (int i = 0; i < EPL; i++) y[i] = x[i];
    solve2(y, x, lane);                       // pass 2: y = pass-1 output

    float* w0 = out + (size_t)(2 * gwarp) * ROWN + lane * EPL;
    float* w1 = w0 + ROWN;
    #pragma unroll
    for (int v = 0; v < EPL / 4; v++) {
        float4 a, b;
        upk(x[4 * v + 0], a.x, b.x);
        upk(x[4 * v + 1], a.y, b.y);
        upk(x[4 * v + 2], a.z, b.z);
        upk(x[4 * v + 3], a.w, b.w);
        reinterpret_cast<float4*>(w0)[v] = a;
        reinterpret_cast<float4*>(w1)[v] = b;
    }
}

extern "C" void kernel_launch(void* const* d_in, const int* in_sizes, int n_in,
                              void* d_out, int out_size)
{
    const float* in = (const float*)d_in[0];
    float* out = (float*)d_out;
    const int nelem  = in_sizes[0];           // 32*512*512
    const int nrows  = nelem / ROWN;          // 16384
    const int npairs = nrows / 2;             // 8192 warps
    const int warps_per_block = 128 / 32;     // 4
    const int nblocks = (npairs + warps_per_block - 1) / warps_per_block;  // 2048
    fista_denoise14_kernel<<<nblocks, 128>>>(in, out);
}

// round 15
// speedup vs baseline: 1.1837x; 1.0301x over previous
#include <cuda_runtime.h>
#include <cstdint>

// FISTA denoiser, packed f32x2, 5-op fused stencil (A*y hoisted as chain
// seed), ghost boundaries, ALL state in registers, occupancy-3.
// One warp = two rows; each u64 register packs (row0[i], row1[i]).
// State: y (clamp bound), ay = A*y (stencil seed), x, z  -> 128 regs.

#define LAM   10.0f
#define NIT   100
#define ROWN  512
#define EPL   16

typedef unsigned long long u64;

__device__ __forceinline__ u64 pk(float lo, float hi) {
    u64 r; asm("mov.b64 %0, {%1,%2};" : "=l"(r) : "f"(lo), "f"(hi)); return r;
}
__device__ __forceinline__ void upk(u64 v, float& lo, float& hi) {
    asm("mov.b64 {%0,%1}, %2;" : "=f"(lo), "=f"(hi) : "l"(v));
}
__device__ __forceinline__ u64 fma2(u64 a, u64 b, u64 c) {
    u64 d; asm("fma.rn.f32x2 %0, %1, %2, %3;" : "=l"(d) : "l"(a), "l"(b), "l"(c)); return d;
}
__device__ __forceinline__ u64 add2(u64 a, u64 b) {
    u64 d; asm("add.rn.f32x2 %0, %1, %2;" : "=l"(d) : "l"(a), "l"(b)); return d;
}
__device__ __forceinline__ u64 mul2(u64 a, u64 b) {
    u64 d; asm("mul.rn.f32x2 %0, %1, %2;" : "=l"(d) : "l"(a), "l"(b)); return d;
}
__device__ __forceinline__ u64 bc(float f) { return pk(f, f); }

// A = 1/(1+16*LAM) = 2*step ; B = LAM/(1+16*LAM) = 2*LAM*step
#define C_A (1.0f / (1.0f + 16.0f * LAM))
#define C_B (LAM  / (1.0f + 16.0f * LAM))

// ---- compile-time FISTA momentum table, pre-broadcast as u64 f32x2 pairs ----
constexpr u64 bcast_bits(float f) {
    unsigned b = __builtin_bit_cast(unsigned, f);
    return ((u64)b << 32) | (u64)b;
}
struct MTab { u64 m1p[NIT]; u64 mn[NIT]; };
constexpr MTab make_mtab() {
    MTab t{};
    double tt = 1.0;
    for (int i = 0; i < NIT; i++) {
        double s = 1.0 + 4.0 * tt * tt;
        double r = s;                         // Newton sqrt
        for (int k = 0; k < 64; k++) r = 0.5 * (r + s / r);
        double tn = 0.5 * (1.0 + r);
        double m  = (tt - 1.0) / tn;
        t.m1p[i] = bcast_bits((float)(1.0 + m));
        t.mn[i]  = bcast_bits((float)(-m));
        tt = tn;
    }
    return t;
}
__constant__ MTab c_mtab = make_mtab();

// One FISTA solve on the packed pair-of-rows.
//   y  : clamp bound (and start point), packed
//   x  : in/out iterate (on entry x == y)
__device__ __forceinline__ void solve2(const u64* __restrict__ y,
                                       u64* __restrict__ x,
                                       int lane)
{
    const unsigned FULL = 0xffffffffu;
    const u64 C0  = bc(1.0f - C_A - 6.0f * C_B);   // center tap
    const u64 C1  = bc(4.0f * C_B);                // +/-1 taps
    const u64 C2  = bc(-C_B);                      // +/-2 taps
    const u64 CAc = bc(C_A);
    const u64 NEG1 = bc(-1.0f);

    // hoisted data term: ay = A*y (chain seed, 16 packed regs)
    u64 ay[EPL], z[EPL];
    #pragma unroll
    for (int i = 0; i < EPL; i++) {
        ay[i] = mul2(CAc, y[i]);
        z[i]  = y[i];                               // proj(y)=y on [0,y]; x==y at entry
    }

    const bool l0 = (lane == 0), l31 = (lane == 31);

    #pragma unroll 2
    for (int it = 0; it < NIT; ++it) {
        // 64-bit halo shuffles
        u64 zm2 = __shfl_up_sync  (FULL, z[EPL - 2], 1);
        u64 zm1 = __shfl_up_sync  (FULL, z[EPL - 1], 1);
        u64 zp0 = __shfl_down_sync(FULL, z[0], 1);
        u64 zp1 = __shfl_down_sync(FULL, z[1], 1);

        // ghost values making the uniform stencil exact at the boundaries
        {
            u64 dl  = fma2(NEG1, z[1], z[0]);              // z0 - z1
            u64 g1  = add2(z[0], dl);                      // 2 z0 - z1
            u64 g2  = add2(g1,  dl);                       // 3 z0 - 2 z1
            u64 dr  = fma2(NEG1, z[EPL - 2], z[EPL - 1]);  // z15 - z14
            u64 g3  = add2(z[EPL - 1], dr);                // 2 z15 - z14
            u64 g4  = add2(g3, dr);                        // 3 z15 - 2 z14
            zm1 = l0  ? g1 : zm1;
            zm2 = l0  ? g2 : zm2;
            zp0 = l31 ? g3 : zp0;
            zp1 = l31 ? g4 : zp1;
        }

        // ze[k] = z_ext[16*lane - 2 + k], k = 0..19  (snapshot of z)
        u64 ze[EPL + 4];
        ze[0] = zm2; ze[1] = zm1;
        #pragma unroll
        for (int i = 0; i < EPL; i++) ze[2 + i] = z[i];
        ze[EPL + 2] = zp0; ze[EPL + 3] = zp1;

        // momentum coefficients (pre-broadcast u64 pairs, one LDC.64 each)
        const u64 M1P = c_mtab.m1p[it];
        const u64 MN  = c_mtab.mn[it];

        // branch-free element loop: 5 packed stencil ops + scalar clamp + 2 packed
        #pragma unroll
        for (int i = 0; i < EPL; i++) {
            // v = ay + C2*(z[-2]+z[+2]) + C1*(z[-1]+z[+1]) + C0*zc
            u64 s1 = add2(ze[i + 1], ze[i + 3]);
            u64 s2 = add2(ze[i],     ze[i + 4]);
            u64 v  = fma2(C0, ze[i + 2],
                       fma2(C1, s1,
                         fma2(C2, s2, ay[i])));

            // clamp onto [0, y] — scalar FMNMX pairs on alu pipe
            float vl, vh, yl, yh;
            upk(v, vl, vh);
            upk(y[i], yl, yh);
            float xl = fminf(fmaxf(vl, 0.0f), yl);
            float xh = fminf(fmaxf(vh, 0.0f), yh);
            u64 xn = pk(xl, xh);

            // z_new = (1+m) x_new - m x_old
            u64 zn = fma2(M1P, xn, mul2(MN, x[i]));
            x[i] = xn;
            z[i] = zn;
        }
    }
}

__global__ void __launch_bounds__(128, 3)
fista_denoise15_kernel(const float* __restrict__ in, float* __restrict__ out)
{
    const int gwarp = (int)((blockIdx.x * (unsigned)blockDim.x + threadIdx.x) >> 5);
    const int lane  = threadIdx.x & 31;
    // grid exactly covers all 8192 pairs: no tail guard

    const float* r0 = in + (size_t)(2 * gwarp) * ROWN + lane * EPL;
    const float* r1 = r0 + ROWN;

    u64 y[EPL];
    #pragma unroll
    for (int v = 0; v < EPL / 4; v++) {
        float4 a = reinterpret_cast<const float4*>(r0)[v];
        float4 b = reinterpret_cast<const float4*>(r1)[v];
        y[4 * v + 0] = pk(a.x, b.x);
        y[4 * v + 1] = pk(a.y, b.y);
        y[4 * v + 2] = pk(a.z, b.z);
        y[4 * v + 3] = pk(a.w, b.w);
    }

    u64 x[EPL];
    #pragma unroll
    for (int i = 0; i < EPL; i++) x[i] = y[i];
    solve2(y, x, lane);                       // pass 1: y = input

    #pragma unroll
    for (int i = 0; i < EPL; i++) y[i] = x[i];
    solve2(y, x, lane);                       // pass 2: y = pass-1 output

    float* w0 = out + (size_t)(2 * gwarp) * ROWN + lane * EPL;
    float* w1 = w0 + ROWN;
    #pragma unroll
    for (int v = 0; v < EPL / 4; v++) {
        float4 a, b;
        upk(x[4 * v + 0], a.x, b.x);
        upk(x[4 * v + 1], a.y, b.y);
        upk(x[4 * v + 2], a.z, b.z);
        upk(x[4 * v + 3], a.w, b.w);
        reinterpret_cast<float4*>(w0)[v] = a;
        reinterpret_cast<float4*>(w1)[v] = b;
    }
}

extern "C" void kernel_launch(void* const* d_in, const int* in_sizes, int n_in,
                              void* d_out, int out_size)
{
    const float* in = (const float*)d_in[0];
    float* out = (float*)d_out;
    const int nelem  = in_sizes[0];           // 32*512*512
    const int nrows  = nelem / ROWN;          // 16384
    const int npairs = nrows / 2;             // 8192 warps
    const int warps_per_block = 128 / 32;     // 4
    const int nblocks = (npairs + warps_per_block - 1) / warps_per_block;  // 2048
    fista_denoise15_kernel<<<nblocks, 128>>>(in, out);
}

// round 16
// speedup vs baseline: 1.2560x; 1.0610x over previous
#include <cuda_runtime.h>
#include <cstdint>

// FISTA denoiser, packed f32x2, 5-op fused stencil (A*y hoisted as chain
// seed), ghost boundaries, ALL state in registers, occupancy-3.
// Edges-first element order: elements {0,1,14,15} updated first, next
// iteration's halo SHFLs issued immediately after, 12 interior elements
// hide the SHFL latency. Full ze snapshot keeps ordering semantics exact.
// One warp = two rows; each u64 register packs (row0[i], row1[i]).

#define LAM   10.0f
#define NIT   100
#define ROWN  512
#define EPL   16

typedef unsigned long long u64;

__device__ __forceinline__ u64 pk(float lo, float hi) {
    u64 r; asm("mov.b64 %0, {%1,%2};" : "=l"(r) : "f"(lo), "f"(hi)); return r;
}
__device__ __forceinline__ void upk(u64 v, float& lo, float& hi) {
    asm("mov.b64 {%0,%1}, %2;" : "=f"(lo), "=f"(hi) : "l"(v));
}
__device__ __forceinline__ u64 fma2(u64 a, u64 b, u64 c) {
    u64 d; asm("fma.rn.f32x2 %0, %1, %2, %3;" : "=l"(d) : "l"(a), "l"(b), "l"(c)); return d;
}
__device__ __forceinline__ u64 add2(u64 a, u64 b) {
    u64 d; asm("add.rn.f32x2 %0, %1, %2;" : "=l"(d) : "l"(a), "l"(b)); return d;
}
__device__ __forceinline__ u64 mul2(u64 a, u64 b) {
    u64 d; asm("mul.rn.f32x2 %0, %1, %2;" : "=l"(d) : "l"(a), "l"(b)); return d;
}
__device__ __forceinline__ u64 bc(float f) { return pk(f, f); }

// A = 1/(1+16*LAM) = 2*step ; B = LAM/(1+16*LAM) = 2*LAM*step
#define C_A (1.0f / (1.0f + 16.0f * LAM))
#define C_B (LAM  / (1.0f + 16.0f * LAM))

// ---- compile-time FISTA momentum table, pre-broadcast as u64 f32x2 pairs ----
constexpr u64 bcast_bits(float f) {
    unsigned b = __builtin_bit_cast(unsigned, f);
    return ((u64)b << 32) | (u64)b;
}
struct MTab { u64 m1p[NIT]; u64 mn[NIT]; };
constexpr MTab make_mtab() {
    MTab t{};
    double tt = 1.0;
    for (int i = 0; i < NIT; i++) {
        double s = 1.0 + 4.0 * tt * tt;
        double r = s;                         // Newton sqrt
        for (int k = 0; k < 64; k++) r = 0.5 * (r + s / r);
        double tn = 0.5 * (1.0 + r);
        double m  = (tt - 1.0) / tn;
        t.m1p[i] = bcast_bits((float)(1.0 + m));
        t.mn[i]  = bcast_bits((float)(-m));
        tt = tn;
    }
    return t;
}
__constant__ MTab c_mtab = make_mtab();

// One FISTA solve on the packed pair-of-rows.
//   y  : clamp bound (and start point), packed
//   x  : in/out iterate (on entry x == y)
__device__ __forceinline__ void solve2(const u64* __restrict__ y,
                                       u64* __restrict__ x,
                                       int lane)
{
    const unsigned FULL = 0xffffffffu;
    const u64 C0  = bc(1.0f - C_A - 6.0f * C_B);   // center tap
    const u64 C1  = bc(4.0f * C_B);                // +/-1 taps
    const u64 C2  = bc(-C_B);                      // +/-2 taps
    const u64 CAc = bc(C_A);
    const u64 NEG1 = bc(-1.0f);

    // hoisted data term: ay = A*y (chain seed, 16 packed regs)
    u64 ay[EPL], z[EPL];
    #pragma unroll
    for (int i = 0; i < EPL; i++) {
        ay[i] = mul2(CAc, y[i]);
        z[i]  = y[i];                               // proj(y)=y on [0,y]; x==y at entry
    }

    const bool l0 = (lane == 0), l31 = (lane == 31);

    // prologue: halos for the first iteration
    u64 hm2 = __shfl_up_sync  (FULL, z[EPL - 2], 1);
    u64 hm1 = __shfl_up_sync  (FULL, z[EPL - 1], 1);
    u64 hp0 = __shfl_down_sync(FULL, z[0], 1);
    u64 hp1 = __shfl_down_sync(FULL, z[1], 1);

    #pragma unroll 2
    for (int it = 0; it < NIT; ++it) {
        // ghost values making the uniform stencil exact at the boundaries
        u64 zm2 = hm2, zm1 = hm1, zp0 = hp0, zp1 = hp1;
        {
            u64 dl  = fma2(NEG1, z[1], z[0]);              // z0 - z1
            u64 g1  = add2(z[0], dl);                      // 2 z0 - z1
            u64 g2  = add2(g1,  dl);                       // 3 z0 - 2 z1
            u64 dr  = fma2(NEG1, z[EPL - 2], z[EPL - 1]);  // z15 - z14
            u64 g3  = add2(z[EPL - 1], dr);                // 2 z15 - z14
            u64 g4  = add2(g3, dr);                        // 3 z15 - 2 z14
            zm1 = l0  ? g1 : zm1;
            zm2 = l0  ? g2 : zm2;
            zp0 = l31 ? g3 : zp0;
            zp1 = l31 ? g4 : zp1;
        }

        // ze[k] = z_ext[16*lane - 2 + k], k = 0..19  (snapshot of z)
        u64 ze[EPL + 4];
        ze[0] = zm2; ze[1] = zm1;
        #pragma unroll
        for (int i = 0; i < EPL; i++) ze[2 + i] = z[i];
        ze[EPL + 2] = zp0; ze[EPL + 3] = zp1;

        // momentum coefficients (pre-broadcast u64 pairs, one LDC.64 each)
        const u64 M1P = c_mtab.m1p[it];
        const u64 MN  = c_mtab.mn[it];

        // per-element update: 5-op packed stencil + scalar clamp + 2 packed
        auto elem = [&](int i) {
            u64 s1 = add2(ze[i + 1], ze[i + 3]);
            u64 s2 = add2(ze[i],     ze[i + 4]);
            u64 v  = fma2(C0, ze[i + 2],
                       fma2(C1, s1,
                         fma2(C2, s2, ay[i])));
            float vl, vh, yl, yh;
            upk(v, vl, vh);
            upk(y[i], yl, yh);
            float xl = fminf(fmaxf(vl, 0.0f), yl);
            float xh = fminf(fmaxf(vh, 0.0f), yh);
            u64 xn = pk(xl, xh);
            u64 zn = fma2(M1P, xn, mul2(MN, x[i]));
            x[i] = xn;
            z[i] = zn;
        };

        // ---- edges first: z[0], z[1], z[14], z[15] get their new values ----
        elem(0);
        elem(1);
        elem(EPL - 2);
        elem(EPL - 1);

        // ---- issue next iteration's halo SHFLs from the fresh edge values ----
        hm2 = __shfl_up_sync  (FULL, z[EPL - 2], 1);
        hm1 = __shfl_up_sync  (FULL, z[EPL - 1], 1);
        hp0 = __shfl_down_sync(FULL, z[0], 1);
        hp1 = __shfl_down_sync(FULL, z[1], 1);

        // ---- interior elements: ~150 issue slots hiding the SHFL latency ----
        #pragma unroll
        for (int i = 2; i < EPL - 2; i++) elem(i);
    }
}

__global__ void __launch_bounds__(128, 3)
fista_denoise16_kernel(const float* __restrict__ in, float* __restrict__ out)
{
    const int gwarp = (int)((blockIdx.x * (unsigned)blockDim.x + threadIdx.x) >> 5);
    const int lane  = threadIdx.x & 31;
    // grid exactly covers all 8192 pairs: no tail guard

    const float* r0 = in + (size_t)(2 * gwarp) * ROWN + lane * EPL;
    const float* r1 = r0 + ROWN;

    u64 y[EPL];
    #pragma unroll
    for (int v = 0; v < EPL / 4; v++) {
        float4 a = reinterpret_cast<const float4*>(r0)[v];
        float4 b = reinterpret_cast<const float4*>(r1)[v];
        y[4 * v + 0] = pk(a.x, b.x);
        y[4 * v + 1] = pk(a.y, b.y);
        y[4 * v + 2] = pk(a.z, b.z);
        y[4 * v + 3] = pk(a.w, b.w);
    }

    u64 x[EPL];
    #pragma unroll
    for (int i = 0; i < EPL; i++) x[i] = y[i];
    solve2(y, x, lane);                       // pass 1: y = input

    #pragma unroll
    for (int i = 0; i < EPL; i++) y[i] = x[i];
    solve2(y, x, lane);                       // pass 2: y = pass-1 output

    float* w0 = out + (size_t)(2 * gwarp) * ROWN + lane * EPL;
    float* w1 = w0 + ROWN;
    #pragma unroll
    for (int v = 0; v < EPL / 4; v++) {
        float4 a, b;
        upk(x[4 * v + 0], a.x, b.x);
        upk(x[4 * v + 1], a.y, b.y);
        upk(x[4 * v + 2], a.z, b.z);
        upk(x[4 * v + 3], a.w, b.w);
        reinterpret_cast<float4*>(w0)[v] = a;
        reinterpret_cast<float4*>(w1)[v] = b;
    }
}

extern "C" void kernel_launch(void* const* d_in, const int* in_sizes, int n_in,
                              void* d_out, int out_size)
{
    const float* in = (const float*)d_in[0];
    float* out = (float*)d_out;
    const int nelem  = in_sizes[0];           // 32*512*512
    const int nrows  = nelem / ROWN;          // 16384
    const int npairs = nrows / 2;             // 8192 warps
    const int warps_per_block = 128 / 32;     // 4
    const int nblocks = (npairs + warps_per_block - 1) / warps_per_block;  // 2048
    fista_denoise16_kernel<<<nblocks, 128>>>(in, out);
}